// round 5
// baseline (speedup 1.0000x reference)
#include <cuda_runtime.h>

#define S_LEN   2048
#define D_MODEL 1024
#define NHEAD   16
#define HDIM    64
#define BATCH   2
#define M_ROWS  (BATCH * S_LEN)   // 4096

// ---------------------------------------------------------------------------
// Scratch (device globals: allocation-free per harness rules)
// ---------------------------------------------------------------------------
__device__ float g_Q[BATCH * NHEAD * S_LEN * HDIM];   // [B*H, S, Hd]
__device__ float g_K[BATCH * NHEAD * S_LEN * HDIM];
__device__ float g_V[BATCH * NHEAD * S_LEN * HDIM];
__device__ float g_C[M_ROWS * D_MODEL];               // attention context [B*S, D]

__device__ __forceinline__ float ex2f_fast(float x) {
    float r;
    asm("ex2.approx.ftz.f32 %0, %1;" : "=f"(r) : "f"(x));
    return r;
}

// ---------------------------------------------------------------------------
// SGEMM: C[M=4096, N=1024] = A[4096,1024] @ W[1024,1024]^T + bias
// 128x128 block tile, BK=8, 256 threads, 8x8 register micro-tile.
// MODE 0: QKV (blockIdx.z selects W/bias; scatter into [B*H,S,Hd] layout)
// MODE 1: output projection (A = g_C, row-major output)
// ---------------------------------------------------------------------------
template <int MODE>
__global__ __launch_bounds__(256)
void sgemm128(const float* __restrict__ A,
              const float* __restrict__ W0, const float* __restrict__ W1,
              const float* __restrict__ W2,
              const float* __restrict__ b0, const float* __restrict__ b1,
              const float* __restrict__ b2,
              float* __restrict__ OutExt)
{
    const float* W;
    const float* bias;
    float* out;
    const float* Ause;

    if (MODE == 0) {
        int z = blockIdx.z;
        W    = (z == 0) ? W0 : (z == 1) ? W1 : W2;
        bias = (z == 0) ? b0 : (z == 1) ? b1 : b2;
        out  = (z == 0) ? g_Q : (z == 1) ? g_K : g_V;
        Ause = A;
    } else {
        W    = W0;
        bias = b0;
        out  = OutExt;
        Ause = g_C;
    }

    __shared__ float As[8][128];
    __shared__ float Bs[8][128];

    const int tid = threadIdx.x;
    const int m0  = blockIdx.y * 128;
    const int n0  = blockIdx.x * 128;
    const int ty  = tid >> 4;        // 0..15
    const int tx  = tid & 15;        // 0..15
    const int lr  = tid >> 1;        // 0..127 (row within tile for loads)
    const int lk  = (tid & 1) * 4;   // 0 or 4 (k offset within BK)

    const float* Aptr = Ause + (size_t)(m0 + lr) * D_MODEL + lk;
    const float* Wptr = W    + (size_t)(n0 + lr) * D_MODEL + lk;

    float c[8][8];
#pragma unroll
    for (int i = 0; i < 8; i++)
#pragma unroll
        for (int j = 0; j < 8; j++) c[i][j] = 0.0f;

    for (int k0 = 0; k0 < D_MODEL; k0 += 8) {
        float4 av = *(const float4*)(Aptr + k0);
        float4 wv = *(const float4*)(Wptr + k0);
        __syncthreads();   // protect previous iteration's shared reads
        As[lk + 0][lr] = av.x; As[lk + 1][lr] = av.y;
        As[lk + 2][lr] = av.z; As[lk + 3][lr] = av.w;
        Bs[lk + 0][lr] = wv.x; Bs[lk + 1][lr] = wv.y;
        Bs[lk + 2][lr] = wv.z; Bs[lk + 3][lr] = wv.w;
        __syncthreads();

#pragma unroll
        for (int kk = 0; kk < 8; kk++) {
            float ar[8], br[8];
            *(float4*)(ar)     = *(const float4*)&As[kk][ty * 8];
            *(float4*)(ar + 4) = *(const float4*)&As[kk][ty * 8 + 4];
            *(float4*)(br)     = *(const float4*)&Bs[kk][tx * 8];
            *(float4*)(br + 4) = *(const float4*)&Bs[kk][tx * 8 + 4];
#pragma unroll
            for (int i = 0; i < 8; i++)
#pragma unroll
                for (int j = 0; j < 8; j++)
                    c[i][j] += ar[i] * br[j];
        }
    }

    // Epilogue
#pragma unroll
    for (int i = 0; i < 8; i++) {
        const int m = m0 + ty * 8 + i;
#pragma unroll
        for (int j = 0; j < 8; j++) {
            const int n = n0 + tx * 8 + j;
            const float v = c[i][j] + bias[n];
            if (MODE == 0) {
                // scatter to [B*H, S, Hd]: b = m/2048, s = m%2048, h = n/64, hd = n%64
                const int b  = m >> 11;
                const int s  = m & 2047;
                const int h  = n >> 6;
                const int hd = n & 63;
                out[(((size_t)(b * NHEAD + h)) * S_LEN + s) * HDIM + hd] = v;
            } else {
                out[(size_t)m * D_MODEL + n] = v;
            }
        }
    }
}

// ---------------------------------------------------------------------------
// Flash attention (fp32): Br = Bc = 64, Hd = 64, online softmax.
// grid = (S/64, B*H), block = 256 (16x16 micro-tiling, 4x4 per thread).
// Shared tiles stored transposed so inner loops use only LDS.128.
// ---------------------------------------------------------------------------
#define LDP 68   // padded leading dim (multiple of 4 for float4 alignment)

__global__ __launch_bounds__(256)
void flash_attn()
{
    extern __shared__ float sm[];
    float* Qts  = sm;                  // [hd=64][q=64]  stride LDP
    float* Kts  = Qts + 64 * LDP;      // [hd=64][key=64]
    float* Vs   = Kts + 64 * LDP;      // [key=64][hd=64]
    float* Pts  = Vs  + 64 * LDP;      // [key=64][q=64] (scores/probs, transposed)
    float* red  = Pts + 64 * LDP;      // [4][64]
    float* rowm = red + 4 * 64;        // [64]
    float* rowl = rowm + 64;           // [64]
    float* corr = rowl + 64;           // [64]

    const int tid = threadIdx.x;
    const int bh  = blockIdx.y;        // 0..31
    const int q0  = blockIdx.x * 64;

    const float* Qb = g_Q + ((size_t)bh * S_LEN + q0) * HDIM;
    const float* Kb = g_K + (size_t)bh * S_LEN * HDIM;
    const float* Vb = g_V + (size_t)bh * S_LEN * HDIM;

    // Load Q tile transposed: Qts[hd][q]
    for (int t = tid; t < 1024; t += 256) {
        const int q  = t >> 4;
        const int h4 = (t & 15) << 2;
        float4 v = *(const float4*)&Qb[q * HDIM + h4];
        Qts[(h4 + 0) * LDP + q] = v.x;
        Qts[(h4 + 1) * LDP + q] = v.y;
        Qts[(h4 + 2) * LDP + q] = v.z;
        Qts[(h4 + 3) * LDP + q] = v.w;
    }
    if (tid < 64) { rowm[tid] = -1e30f; rowl[tid] = 0.0f; }

    const int ty = tid >> 4;   // q group: queries ty*4 .. ty*4+3
    const int tx = tid & 15;   // key group (score phase) / hd group (PV phase)
    const int qv = tid & 63;   // query handled in softmax phase
    const int part = tid >> 6; // 0..3

    float o[4][4];
#pragma unroll
    for (int i = 0; i < 4; i++)
#pragma unroll
        for (int j = 0; j < 4; j++) o[i][j] = 0.0f;

    // scaling * log2(e): scores computed directly in log2 domain
    const float SCL = 0.125f * 1.4426950408889634f;

    for (int kt = 0; kt < S_LEN / 64; kt++) {
        const float* Kt = Kb + (size_t)kt * 64 * HDIM;
        const float* Vt = Vb + (size_t)kt * 64 * HDIM;

        __syncthreads();   // prior-iteration Pts/Vs reads done before overwrite
        for (int t = tid; t < 1024; t += 256) {
            const int r  = t >> 4;
            const int h4 = (t & 15) << 2;
            float4 kv = *(const float4*)&Kt[r * HDIM + h4];
            Kts[(h4 + 0) * LDP + r] = kv.x;
            Kts[(h4 + 1) * LDP + r] = kv.y;
            Kts[(h4 + 2) * LDP + r] = kv.z;
            Kts[(h4 + 3) * LDP + r] = kv.w;
            float4 vv = *(const float4*)&Vt[r * HDIM + h4];
            *(float4*)&Vs[r * LDP + h4] = vv;
        }
        __syncthreads();

        // ---- scores: s[key][q] = sum_hd Q[q][hd] * K[key][hd] ----
        float s[4][4];
#pragma unroll
        for (int i = 0; i < 4; i++)
#pragma unroll
            for (int j = 0; j < 4; j++) s[i][j] = 0.0f;

#pragma unroll 8
        for (int kk = 0; kk < HDIM; kk++) {
            float4 a = *(const float4*)&Qts[kk * LDP + ty * 4];
            float4 b = *(const float4*)&Kts[kk * LDP + tx * 4];
            float aq[4] = {a.x, a.y, a.z, a.w};
            float bk[4] = {b.x, b.y, b.z, b.w};
#pragma unroll
            for (int ki = 0; ki < 4; ki++)
#pragma unroll
                for (int qj = 0; qj < 4; qj++)
                    s[ki][qj] += bk[ki] * aq[qj];
        }
#pragma unroll
        for (int ki = 0; ki < 4; ki++)
#pragma unroll
            for (int qj = 0; qj < 4; qj++)
                Pts[(tx * 4 + ki) * LDP + ty * 4 + qj] = s[ki][qj] * SCL;
        __syncthreads();

        // ---- online softmax over key dim (per query column) ----
        {
            float mx = -1e30f;
            const int kbeg = part * 16;
#pragma unroll
            for (int k = 0; k < 16; k++)
                mx = fmaxf(mx, Pts[(kbeg + k) * LDP + qv]);
            red[part * 64 + qv] = mx;
        }
        __syncthreads();
        if (part == 0) {
            float m4 = fmaxf(fmaxf(red[qv], red[64 + qv]),
                             fmaxf(red[128 + qv], red[192 + qv]));
            float old = rowm[qv];
            float nm  = fmaxf(old, m4);
            rowm[qv] = nm;
            corr[qv] = ex2f_fast(old - nm);
        }
        __syncthreads();
        {
            const float nm = rowm[qv];
            float ls = 0.0f;
            const int kbeg = part * 16;
#pragma unroll
            for (int k = 0; k < 16; k++) {
                const int idx = (kbeg + k) * LDP + qv;
                float p = ex2f_fast(Pts[idx] - nm);
                Pts[idx] = p;
                ls += p;
            }
            red[part * 64 + qv] = ls;
        }
        __syncthreads();
        if (part == 0) {
            rowl[qv] = rowl[qv] * corr[qv] +
                       red[qv] + red[64 + qv] + red[128 + qv] + red[192 + qv];
        }

        // rescale accumulated output rows by correction factor
        {
            float cr[4];
#pragma unroll
            for (int qj = 0; qj < 4; qj++) cr[qj] = corr[ty * 4 + qj];
#pragma unroll
            for (int qj = 0; qj < 4; qj++)
#pragma unroll
                for (int hj = 0; hj < 4; hj++)
                    o[qj][hj] *= cr[qj];
        }

        // ---- O += P @ V : o[q][hd] += sum_key P[key][q] * V[key][hd] ----
#pragma unroll 8
        for (int kk = 0; kk < 64; kk++) {
            float4 p  = *(const float4*)&Pts[kk * LDP + ty * 4];
            float4 vv = *(const float4*)&Vs[kk * LDP + tx * 4];
            float pq[4] = {p.x, p.y, p.z, p.w};
            float vh[4] = {vv.x, vv.y, vv.z, vv.w};
#pragma unroll
            for (int qj = 0; qj < 4; qj++)
#pragma unroll
                for (int hj = 0; hj < 4; hj++)
                    o[qj][hj] += pq[qj] * vh[hj];
        }
    }

    __syncthreads();   // rowl final values visible
    const int b = bh >> 4;
    const int h = bh & 15;
#pragma unroll
    for (int qj = 0; qj < 4; qj++) {
        const float inv = 1.0f / rowl[ty * 4 + qj];
        const size_t row = (size_t)b * S_LEN + q0 + ty * 4 + qj;
        float4 res;
        res.x = o[qj][0] * inv;
        res.y = o[qj][1] * inv;
        res.z = o[qj][2] * inv;
        res.w = o[qj][3] * inv;
        *(float4*)&g_C[row * D_MODEL + h * HDIM + tx * 4] = res;
    }
}

// ---------------------------------------------------------------------------
// Launch
// ---------------------------------------------------------------------------
extern "C" void kernel_launch(void* const* d_in, const int* in_sizes, int n_in,
                              void* d_out, int out_size)
{
    const float* x  = (const float*)d_in[0];
    const float* Wq = (const float*)d_in[1];
    const float* bq = (const float*)d_in[2];
    const float* Wk = (const float*)d_in[3];
    const float* bk = (const float*)d_in[4];
    const float* Wv = (const float*)d_in[5];
    const float* bv = (const float*)d_in[6];
    const float* Wo = (const float*)d_in[7];
    const float* bo = (const float*)d_in[8];
    float* out = (float*)d_out;

    const int smem_bytes = (4 * 64 * LDP + 4 * 64 + 3 * 64) * (int)sizeof(float);
    cudaFuncSetAttribute(flash_attn,
                         cudaFuncAttributeMaxDynamicSharedMemorySize, smem_bytes);

    // 1) fused QKV projections
    {
        dim3 grid(D_MODEL / 128, M_ROWS / 128, 3);
        sgemm128<0><<<grid, 256>>>(x, Wq, Wk, Wv, bq, bk, bv, nullptr);
    }
    // 2) flash attention
    {
        dim3 grid(S_LEN / 64, BATCH * NHEAD);
        flash_attn<<<grid, 256, smem_bytes>>>();
    }
    // 3) output projection
    {
        dim3 grid(D_MODEL / 128, M_ROWS / 128, 1);
        sgemm128<1><<<grid, 256>>>(nullptr, Wo, nullptr, nullptr,
                                   bo, nullptr, nullptr, out);
    }
}

// round 8
// speedup vs baseline: 1.0289x; 1.0289x over previous
#include <cuda_runtime.h>

#define S_LEN   2048
#define D_MODEL 1024
#define NHEAD   16
#define HDIM    64
#define BATCH   2
#define M_ROWS  (BATCH * S_LEN)   // 4096

// ---------------------------------------------------------------------------
// Scratch (device globals: allocation-free per harness rules)
// ---------------------------------------------------------------------------
__device__ float g_Q[BATCH * NHEAD * S_LEN * HDIM];   // [B*H, S, Hd]
__device__ float g_K[BATCH * NHEAD * S_LEN * HDIM];
__device__ float g_V[BATCH * NHEAD * S_LEN * HDIM];
__device__ float g_C[M_ROWS * D_MODEL];               // attention context [B*S, D]

__device__ __forceinline__ float ex2f_fast(float x) {
    float r;
    asm("ex2.approx.ftz.f32 %0, %1;" : "=f"(r) : "f"(x));
    return r;
}

// ---------------------------------------------------------------------------
// SGEMM: C[M=4096, N=1024] = A[4096,1024] @ W[1024,1024]^T + bias
// 128x128 block tile, BK=8, 256 threads, 8x8 micro-tile.
// Double-buffered smem, LDG for block k+1 issued before compute of block k,
// ONE __syncthreads per k-block. Smem rows padded to 132 (conflict-free STS).
// MODE 0: QKV (blockIdx.z selects W/bias; scatter into [B*H,S,Hd] layout)
// MODE 1: output projection (A = g_C, row-major output)
// ---------------------------------------------------------------------------
#define SLD 132   // padded smem row length (132*4 % 16 == 0, bank-shifted)

template <int MODE>
__global__ __launch_bounds__(256)
void sgemm128(const float* __restrict__ A,
              const float* __restrict__ W0, const float* __restrict__ W1,
              const float* __restrict__ W2,
              const float* __restrict__ b0, const float* __restrict__ b1,
              const float* __restrict__ b2,
              float* __restrict__ OutExt)
{
    const float* W;
    const float* bias;
    float* out;
    const float* Ause;

    if (MODE == 0) {
        int z = blockIdx.z;
        W    = (z == 0) ? W0 : (z == 1) ? W1 : W2;
        bias = (z == 0) ? b0 : (z == 1) ? b1 : b2;
        out  = (z == 0) ? g_Q : (z == 1) ? g_K : g_V;
        Ause = A;
    } else {
        W    = W0;
        bias = b0;
        out  = OutExt;
        Ause = g_C;
    }

    __shared__ float As[2][8][SLD];
    __shared__ float Bs[2][8][SLD];

    const int tid = threadIdx.x;
    const int m0  = blockIdx.y * 128;
    const int n0  = blockIdx.x * 128;
    const int ty  = tid >> 4;        // 0..15
    const int tx  = tid & 15;        // 0..15
    const int lr  = tid >> 1;        // 0..127 (row within tile for loads)
    const int lk  = (tid & 1) * 4;   // 0 or 4 (k offset within BK)

    const float* Aptr = Ause + (size_t)(m0 + lr) * D_MODEL + lk;
    const float* Wptr = W    + (size_t)(n0 + lr) * D_MODEL + lk;

    // prologue: load k-block 0 into buffer 0
    {
        float4 av = *(const float4*)(Aptr);
        float4 wv = *(const float4*)(Wptr);
        As[0][lk + 0][lr] = av.x; As[0][lk + 1][lr] = av.y;
        As[0][lk + 2][lr] = av.z; As[0][lk + 3][lr] = av.w;
        Bs[0][lk + 0][lr] = wv.x; Bs[0][lk + 1][lr] = wv.y;
        Bs[0][lk + 2][lr] = wv.z; Bs[0][lk + 3][lr] = wv.w;
    }
    __syncthreads();

    float c[8][8];
#pragma unroll
    for (int i = 0; i < 8; i++)
#pragma unroll
        for (int j = 0; j < 8; j++) c[i][j] = 0.0f;

    const int NKB = D_MODEL / 8;   // 128
    for (int kb = 0; kb < NKB; kb++) {
        const int cur = kb & 1;
        float4 an, wn;
        if (kb < NKB - 1) {
            an = *(const float4*)(Aptr + (kb + 1) * 8);
            wn = *(const float4*)(Wptr + (kb + 1) * 8);
        }

#pragma unroll
        for (int kk = 0; kk < 8; kk++) {
            float ar[8], br[8];
            *(float4*)(ar)     = *(const float4*)&As[cur][kk][ty * 8];
            *(float4*)(ar + 4) = *(const float4*)&As[cur][kk][ty * 8 + 4];
            *(float4*)(br)     = *(const float4*)&Bs[cur][kk][tx * 8];
            *(float4*)(br + 4) = *(const float4*)&Bs[cur][kk][tx * 8 + 4];
#pragma unroll
            for (int i = 0; i < 8; i++)
#pragma unroll
                for (int j = 0; j < 8; j++)
                    c[i][j] += ar[i] * br[j];
        }

        if (kb < NKB - 1) {
            const int nxt = cur ^ 1;
            As[nxt][lk + 0][lr] = an.x; As[nxt][lk + 1][lr] = an.y;
            As[nxt][lk + 2][lr] = an.z; As[nxt][lk + 3][lr] = an.w;
            Bs[nxt][lk + 0][lr] = wn.x; Bs[nxt][lk + 1][lr] = wn.y;
            Bs[nxt][lk + 2][lr] = wn.z; Bs[nxt][lk + 3][lr] = wn.w;
        }
        __syncthreads();
    }

    // Epilogue (vectorized: 8 consecutive n stay inside one head for MODE 0)
    float bv[8];
    *(float4*)(bv)     = *(const float4*)&bias[n0 + tx * 8];
    *(float4*)(bv + 4) = *(const float4*)&bias[n0 + tx * 8 + 4];

#pragma unroll
    for (int i = 0; i < 8; i++) {
        const int m = m0 + ty * 8 + i;
        const int n = n0 + tx * 8;
        float4 r0, r1;
        r0.x = c[i][0] + bv[0]; r0.y = c[i][1] + bv[1];
        r0.z = c[i][2] + bv[2]; r0.w = c[i][3] + bv[3];
        r1.x = c[i][4] + bv[4]; r1.y = c[i][5] + bv[5];
        r1.z = c[i][6] + bv[6]; r1.w = c[i][7] + bv[7];
        if (MODE == 0) {
            const int b  = m >> 11;
            const int s  = m & 2047;
            const int h  = n >> 6;
            const int hd = n & 63;
            float* p = out + (((size_t)(b * NHEAD + h)) * S_LEN + s) * HDIM + hd;
            *(float4*)(p)     = r0;
            *(float4*)(p + 4) = r1;
        } else {
            float* p = out + (size_t)m * D_MODEL + n;
            *(float4*)(p)     = r0;
            *(float4*)(p + 4) = r1;
        }
    }
}

// ---------------------------------------------------------------------------
// Flash attention (fp32): Br = Bc = 64, Hd = 64, online softmax in REGISTERS.
// grid = (S/64, B*H), block = 256 (16x16 micro-tiling, 4x4 per thread).
// Row of 64 keys for a query lives in 16 consecutive lanes (tx = tid&15):
// softmax max/sum via shfl.xor {1,2,4,8}; running m/l/corr in registers.
// K/V for tile kt+1 prefetched into registers during compute of tile kt.
// 3 barriers per iteration.
// ---------------------------------------------------------------------------
#define LDP 68   // padded leading dim (multiple of 4 for float4 alignment)

__global__ __launch_bounds__(256)
void flash_attn()
{
    extern __shared__ float sm[];
    float* Qts = sm;               // [hd=64][q=64]   stride LDP
    float* Kts = Qts + 64 * LDP;   // [hd=64][key=64]
    float* Vs  = Kts + 64 * LDP;   // [key=64][hd=64]
    float* Pts = Vs  + 64 * LDP;   // [key=64][q=64]

    const int tid = threadIdx.x;
    const int bh  = blockIdx.y;        // 0..31
    const int q0  = blockIdx.x * 64;

    const float* Qb = g_Q + ((size_t)bh * S_LEN + q0) * HDIM;
    const float* Kb = g_K + (size_t)bh * S_LEN * HDIM;
    const float* Vb = g_V + (size_t)bh * S_LEN * HDIM;

    const int ty = tid >> 4;   // q group: queries ty*4 .. ty*4+3
    const int tx = tid & 15;   // key group (scores) / hd group (PV)

    // Load Q tile transposed: Qts[hd][q]
    for (int t = tid; t < 1024; t += 256) {
        const int q  = t >> 4;
        const int h4 = (t & 15) << 2;
        float4 v = *(const float4*)&Qb[q * HDIM + h4];
        Qts[(h4 + 0) * LDP + q] = v.x;
        Qts[(h4 + 1) * LDP + q] = v.y;
        Qts[(h4 + 2) * LDP + q] = v.z;
        Qts[(h4 + 3) * LDP + q] = v.w;
    }

    // Stage K/V tile 0 into registers
    float4 kf[4], vf[4];
#pragma unroll
    for (int cnk = 0; cnk < 4; cnk++) {
        const int t  = tid + cnk * 256;
        const int r  = t >> 4;
        const int h4 = (t & 15) << 2;
        kf[cnk] = *(const float4*)&Kb[r * HDIM + h4];
        vf[cnk] = *(const float4*)&Vb[r * HDIM + h4];
    }

    float o[4][4];
    float m_run[4], l_run[4];
#pragma unroll
    for (int i = 0; i < 4; i++) {
        m_run[i] = -1e30f;
        l_run[i] = 0.0f;
#pragma unroll
        for (int j = 0; j < 4; j++) o[i][j] = 0.0f;
    }

    // scaling * log2(e): exp computed in log2 domain
    const float SCL = 0.125f * 1.4426950408889634f;

    for (int kt = 0; kt < S_LEN / 64; kt++) {
        __syncthreads();   // prior-iteration Pts/Vs/Kts reads done (iter 0: Qts writes)

        // commit staged K (transposed) and V into smem
#pragma unroll
        for (int cnk = 0; cnk < 4; cnk++) {
            const int t  = tid + cnk * 256;
            const int r  = t >> 4;
            const int h4 = (t & 15) << 2;
            Kts[(h4 + 0) * LDP + r] = kf[cnk].x;
            Kts[(h4 + 1) * LDP + r] = kf[cnk].y;
            Kts[(h4 + 2) * LDP + r] = kf[cnk].z;
            Kts[(h4 + 3) * LDP + r] = kf[cnk].w;
            *(float4*)&Vs[r * LDP + h4] = vf[cnk];
        }
        __syncthreads();

        // prefetch next K/V tile into registers (overlaps with compute below)
        if (kt < S_LEN / 64 - 1) {
            const float* Kt = Kb + (size_t)(kt + 1) * 64 * HDIM;
            const float* Vt = Vb + (size_t)(kt + 1) * 64 * HDIM;
#pragma unroll
            for (int cnk = 0; cnk < 4; cnk++) {
                const int t  = tid + cnk * 256;
                const int r  = t >> 4;
                const int h4 = (t & 15) << 2;
                kf[cnk] = *(const float4*)&Kt[r * HDIM + h4];
                vf[cnk] = *(const float4*)&Vt[r * HDIM + h4];
            }
        }

        // ---- scores: s[key][q] = sum_hd Q[q][hd] * K[key][hd] ----
        float s[4][4];
#pragma unroll
        for (int i = 0; i < 4; i++)
#pragma unroll
            for (int j = 0; j < 4; j++) s[i][j] = 0.0f;

#pragma unroll 8
        for (int kk = 0; kk < HDIM; kk++) {
            float4 a = *(const float4*)&Qts[kk * LDP + ty * 4];
            float4 b = *(const float4*)&Kts[kk * LDP + tx * 4];
            float aq[4] = {a.x, a.y, a.z, a.w};
            float bk[4] = {b.x, b.y, b.z, b.w};
#pragma unroll
            for (int ki = 0; ki < 4; ki++)
#pragma unroll
                for (int qj = 0; qj < 4; qj++)
                    s[ki][qj] += bk[ki] * aq[qj];
        }

        // ---- online softmax entirely in registers (shfl over the 16-lane
        //      key-group; xor masks 1,2,4,8 stay inside the group) ----
        float corr_[4];
#pragma unroll
        for (int qj = 0; qj < 4; qj++) {
            float mx = -1e30f;
#pragma unroll
            for (int ki = 0; ki < 4; ki++) {
                const float t = s[ki][qj] * SCL;
                s[ki][qj] = t;
                mx = fmaxf(mx, t);
            }
            mx = fmaxf(mx, __shfl_xor_sync(0xffffffffu, mx, 1));
            mx = fmaxf(mx, __shfl_xor_sync(0xffffffffu, mx, 2));
            mx = fmaxf(mx, __shfl_xor_sync(0xffffffffu, mx, 4));
            mx = fmaxf(mx, __shfl_xor_sync(0xffffffffu, mx, 8));

            const float mn = fmaxf(m_run[qj], mx);
            corr_[qj] = ex2f_fast(m_run[qj] - mn);
            m_run[qj] = mn;

            float ls = 0.0f;
#pragma unroll
            for (int ki = 0; ki < 4; ki++) {
                const float p = ex2f_fast(s[ki][qj] - mn);
                s[ki][qj] = p;
                ls += p;
            }
            ls += __shfl_xor_sync(0xffffffffu, ls, 1);
            ls += __shfl_xor_sync(0xffffffffu, ls, 2);
            ls += __shfl_xor_sync(0xffffffffu, ls, 4);
            ls += __shfl_xor_sync(0xffffffffu, ls, 8);
            l_run[qj] = l_run[qj] * corr_[qj] + ls;
        }

        // write P^T once, rescale o by correction
#pragma unroll
        for (int ki = 0; ki < 4; ki++)
#pragma unroll
            for (int qj = 0; qj < 4; qj++)
                Pts[(tx * 4 + ki) * LDP + ty * 4 + qj] = s[ki][qj];

#pragma unroll
        for (int qj = 0; qj < 4; qj++)
#pragma unroll
            for (int hj = 0; hj < 4; hj++)
                o[qj][hj] *= corr_[qj];

        __syncthreads();

        // ---- O += P @ V : o[q][hd] += sum_key P[key][q] * V[key][hd] ----
#pragma unroll 8
        for (int kk = 0; kk < 64; kk++) {
            float4 p  = *(const float4*)&Pts[kk * LDP + ty * 4];
            float4 vv = *(const float4*)&Vs[kk * LDP + tx * 4];
            float pq[4] = {p.x, p.y, p.z, p.w};
            float vh[4] = {vv.x, vv.y, vv.z, vv.w};
#pragma unroll
            for (int qj = 0; qj < 4; qj++)
#pragma unroll
                for (int hj = 0; hj < 4; hj++)
                    o[qj][hj] += pq[qj] * vh[hj];
        }
    }

    // epilogue: normalize and write context
    const int b = bh >> 4;
    const int h = bh & 15;
#pragma unroll
    for (int qj = 0; qj < 4; qj++) {
        const float inv = 1.0f / l_run[qj];
        const size_t row = (size_t)b * S_LEN + q0 + ty * 4 + qj;
        float4 res;
        res.x = o[qj][0] * inv;
        res.y = o[qj][1] * inv;
        res.z = o[qj][2] * inv;
        res.w = o[qj][3] * inv;
        *(float4*)&g_C[row * D_MODEL + h * HDIM + tx * 4] = res;
    }
}

// ---------------------------------------------------------------------------
// Launch
// ---------------------------------------------------------------------------
extern "C" void kernel_launch(void* const* d_in, const int* in_sizes, int n_in,
                              void* d_out, int out_size)
{
    const float* x  = (const float*)d_in[0];
    const float* Wq = (const float*)d_in[1];
    const float* bq = (const float*)d_in[2];
    const float* Wk = (const float*)d_in[3];
    const float* bk = (const float*)d_in[4];
    const float* Wv = (const float*)d_in[5];
    const float* bv = (const float*)d_in[6];
    const float* Wo = (const float*)d_in[7];
    const float* bo = (const float*)d_in[8];
    float* out = (float*)d_out;

    const int smem_bytes = (4 * 64 * LDP) * (int)sizeof(float);
    cudaFuncSetAttribute(flash_attn,
                         cudaFuncAttributeMaxDynamicSharedMemorySize, smem_bytes);

    // 1) fused QKV projections
    {
        dim3 grid(D_MODEL / 128, M_ROWS / 128, 3);
        sgemm128<0><<<grid, 256>>>(x, Wq, Wk, Wv, bq, bk, bv, nullptr);
    }
    // 2) flash attention
    {
        dim3 grid(S_LEN / 64, BATCH * NHEAD);
        flash_attn<<<grid, 256, smem_bytes>>>();
    }
    // 3) output projection
    {
        dim3 grid(D_MODEL / 128, M_ROWS / 128, 1);
        sgemm128<1><<<grid, 256>>>(nullptr, Wo, nullptr, nullptr,
                                   bo, nullptr, nullptr, out);
    }
}